// round 16
// baseline (speedup 1.0000x reference)
#include <cuda_runtime.h>
#include <cuda_bf16.h>
#include <math.h>
#include <stdint.h>

#define BB    8
#define CIN   256
#define OUTC  256
#define SHAREC 8
#define GG    32
#define MID   320
#define MIDP  384
#define WOUT  288
#define P     4096

// ---------------- scratch (static device arrays; no allocation) ----------------
__device__ float g_y[(size_t)BB * MID * P];      // conv1x1 outputs [b][c][p]
__device__ float g_w[(size_t)BB * WOUT * P];     // per-pixel kernels [b][o][p]
__device__ float g_bias[MIDP];
__device__ float g_bn1s[MID];
__device__ float g_bn1b[MID];
__device__ float g_bn2s[GG];
__device__ float g_bn2b[GG];
__device__ __nv_bfloat16 g_whi[MIDP * CIN];      // conv weights hi/lo, [m][k]
__device__ __nv_bfloat16 g_wlo[MIDP * CIN];
__device__ __nv_bfloat16 g_c1hi[GG * MID];       // cw1 hi/lo, [g][k]
__device__ __nv_bfloat16 g_c1lo[GG * MID];
__device__ __nv_bfloat16 g_c2hi[WOUT * GG];      // cw2 hi/lo, [o][k]
__device__ __nv_bfloat16 g_c2lo[WOUT * GG];
__device__ __nv_bfloat16 g_thi[(size_t)BB * P * GG];   // t hi/lo: [b][p][g]
__device__ __nv_bfloat16 g_tlo[(size_t)BB * P * GG];

__device__ __forceinline__ uint32_t smem_u32(const void* p) {
    uint32_t a;
    asm("{ .reg .u64 t; cvta.to.shared.u64 t, %1; cvt.u32.u64 %0, t; }" : "=r"(a) : "l"(p));
    return a;
}

#define LDSM4(r0, r1, r2, r3, addr) \
    asm volatile("ldmatrix.sync.aligned.m8n8.x4.shared.b16 {%0,%1,%2,%3}, [%4];" \
        : "=r"(r0), "=r"(r1), "=r"(r2), "=r"(r3) : "r"(addr))

#define MMA_BF16(d, a, b) \
    asm volatile("mma.sync.aligned.m16n8k16.row.col.f32.bf16.bf16.f32 " \
        "{%0,%1,%2,%3}, {%4,%5,%6,%7}, {%8,%9}, {%0,%1,%2,%3};" \
        : "+f"((d)[0]), "+f"((d)[1]), "+f"((d)[2]), "+f"((d)[3]) \
        : "r"((a)[0]), "r"((a)[1]), "r"((a)[2]), "r"((a)[3]), "r"((b)[0]), "r"((b)[1]))

#define CP_ASYNC16(saddr, gptr) \
    asm volatile("cp.async.cg.shared.global [%0], [%1], 16;" :: "r"(saddr), "l"(gptr))
#define CP_COMMIT() asm volatile("cp.async.commit_group;" ::: "memory")
#define CP_WAIT1()  asm volatile("cp.async.wait_group 1;" ::: "memory")
#define CP_WAIT0()  asm volatile("cp.async.wait_group 0;" ::: "memory")

// ---------------- K0: pack + split weights + fold BN (single launch) ----------------
__global__ __launch_bounds__(256) void pack_kernel(const float* __restrict__ w1,
                                                   const float* __restrict__ w2,
                                                   const float* __restrict__ w3,
                                                   const float* __restrict__ cw1,
                                                   const float* __restrict__ cw2,
                                                   const float* __restrict__ b1,
                                                   const float* __restrict__ b2,
                                                   const float* __restrict__ b3,
                                                   const float* __restrict__ bn1_g,
                                                   const float* __restrict__ bn1_b,
                                                   const float* __restrict__ bn1_m,
                                                   const float* __restrict__ bn1_v,
                                                   const float* __restrict__ bn2_g,
                                                   const float* __restrict__ bn2_b,
                                                   const float* __restrict__ bn2_m,
                                                   const float* __restrict__ bn2_v) {
    int idx = blockIdx.x * 256 + threadIdx.x;
    if (idx < MIDP * CIN) {
        int c = idx >> 8;
        int k = idx & 255;
        float v = 0.f;
        if (c < 32)       v = w1[c * CIN + k];
        else if (c < 64)  v = w2[(c - 32) * CIN + k];
        else if (c < MID) v = w3[(c - 64) * CIN + k];
        __nv_bfloat16 hi = __float2bfloat16(v);
        g_whi[idx] = hi;
        g_wlo[idx] = __float2bfloat16(v - __bfloat162float(hi));
    } else if (idx < MIDP * CIN + GG * MID) {
        int j = idx - MIDP * CIN;
        float v = cw1[j];
        __nv_bfloat16 hi = __float2bfloat16(v);
        g_c1hi[j] = hi;
        g_c1lo[j] = __float2bfloat16(v - __bfloat162float(hi));
    } else if (idx < MIDP * CIN + GG * MID + WOUT * GG) {
        int j = idx - MIDP * CIN - GG * MID;
        float v = cw2[j];
        __nv_bfloat16 hi = __float2bfloat16(v);
        g_c2hi[j] = hi;
        g_c2lo[j] = __float2bfloat16(v - __bfloat162float(hi));
    } else {
        int c = idx - MIDP * CIN - GG * MID - WOUT * GG;
        if (c < MID) {
            g_bias[c] = (c < 32) ? b1[c] : (c < 64) ? b2[c - 32] : b3[c - 64];
            float s = bn1_g[c] * rsqrtf(bn1_v[c] + 1e-5f);
            g_bn1s[c] = s;
            g_bn1b[c] = bn1_b[c] - bn1_m[c] * s;
            if (c < GG) {
                float s2 = bn2_g[c] * rsqrtf(bn2_v[c] + 1e-5f);
                g_bn2s[c] = s2;
                g_bn2b[c] = bn2_b[c] - bn2_m[c] * s2;
            }
        } else if (c < MID + MIDP - MID) {
            g_bias[c] = 0.f;   // padded bias rows (unused but keep defined)
        }
    }
}

// ---------------- K1: conv1x1 split-bf16 GEMM, M64 x N64 tiles (no padding waste) ----------
// grid: (P/64, MID/64=5, BB). Per CTA: K=256 in 4 chunks; A + raw fp32 x double-buffered,
// x converted in-kernel to single-buffered swizzled B tile. 2 CTAs/SM.
#define KC 64
#define ST_AHI 0
#define ST_ALO 8192
#define ST_X   16384
#define STAGE  32768
#define CB_HI  65536
#define CB_LO  73728
#define SM_TOTAL 81920

__global__ __launch_bounds__(256, 2) void conv_mma_kernel(const float* __restrict__ x) {
    extern __shared__ char smem[];
    const uint32_t sbase = smem_u32(smem);
    const int tid = threadIdx.x;
    const int wid = tid >> 5;
    const int lid = tid & 31;
    const int b  = blockIdx.z;
    const int m0 = blockIdx.y * 64;
    const int p0 = blockIdx.x * 64;
    const int wm = wid & 1;      // 2 warps along M (32 m each)
    const int wn = wid >> 1;     // 4 warps along N (16 px each)

    float acc[2][2][4];
#pragma unroll
    for (int i = 0; i < 2; i++)
#pragma unroll
        for (int j = 0; j < 2; j++)
#pragma unroll
            for (int q = 0; q < 4; q++) acc[i][j][q] = 0.f;

    const int rowA[2] = { wm * 32 + (lid & 15), wm * 32 + 16 + (lid & 15) };
    const int c16A = (lid >> 4) * 16;
    const int rowB = wn * 16 + ((lid >> 4) * 8) + (lid & 7);
    const int c16B = ((lid >> 3) & 1) * 16;

    // A loader: 64 rows x 128B, 2 rows per thread
    const int rowL = tid >> 3;
    const int ccL  = (tid & 7) * 16;
    uint32_t ldstA[2];
    const __nv_bfloat16 *srcAh[2], *srcAl[2];
#pragma unroll
    for (int e = 0; e < 2; e++) {
        int row = rowL + e * 32;
        ldstA[e] = (uint32_t)(row * 128) + (uint32_t)(ccL ^ ((row & 7) * 16));
        size_t sA = (size_t)(m0 + row) * CIN + (ccL >> 1);
        srcAh[e] = &g_whi[sA]; srcAl[e] = &g_wlo[sA];
    }
    // X loader: 64 k-rows x 256B, 4 chunks per thread
    const float* xbase = x + (size_t)b * CIN * P + p0;
    const int kxL = tid >> 4;
    const int uxL = (tid & 15) * 16;

    auto issue = [&](int c, int s) {
        const uint32_t stb = sbase + (uint32_t)(s * STAGE);
        const int koff = c * KC;
#pragma unroll
        for (int e = 0; e < 2; e++) {
            CP_ASYNC16(stb + ST_AHI + ldstA[e], srcAh[e] + koff);
            CP_ASYNC16(stb + ST_ALO + ldstA[e], srcAl[e] + koff);
        }
#pragma unroll
        for (int e = 0; e < 4; e++) {
            int kx = kxL + e * 16;
            CP_ASYNC16(stb + ST_X + (uint32_t)(kx * 256) + (uint32_t)uxL,
                       xbase + (size_t)(koff + kx) * P + (uxL >> 2));
        }
        CP_COMMIT();
    };

    const int cvp = tid & 63;
    const int cvk = (tid >> 6) * 16;

    issue(0, 0);
    for (int c = 0; c < 4; c++) {
        if (c < 3) { issue(c + 1, (c + 1) & 1); CP_WAIT1(); }
        else       { CP_WAIT0(); }
        __syncthreads();

        {
            const char* xs = smem + (c & 1) * STAGE + ST_X;
#pragma unroll
            for (int e = 0; e < 8; e++) {
                int k = cvk + 2 * e;
                float f0 = *(const float*)(xs + k * 256 + cvp * 4);
                float f1 = *(const float*)(xs + (k + 1) * 256 + cvp * 4);
                __nv_bfloat16 h0 = __float2bfloat16(f0);
                __nv_bfloat16 h1 = __float2bfloat16(f1);
                __nv_bfloat16 l0 = __float2bfloat16(f0 - __bfloat162float(h0));
                __nv_bfloat16 l1 = __float2bfloat16(f1 - __bfloat162float(h1));
                uint32_t d = (uint32_t)(cvp * 128) + (uint32_t)((2 * k) ^ ((cvp & 7) * 16));
                *(__nv_bfloat162*)(smem + CB_HI + d) = __nv_bfloat162(h0, h1);
                *(__nv_bfloat162*)(smem + CB_LO + d) = __nv_bfloat162(l0, l1);
            }
        }
        __syncthreads();

        const uint32_t stb = sbase + (uint32_t)((c & 1) * STAGE);
#pragma unroll
        for (int ks = 0; ks < 4; ks++) {
            const int colA = (ks * 32 + c16A);
            const int colB = (ks * 32 + c16B);
            uint32_t ah[2][4], al[2][4];
#pragma unroll
            for (int mf = 0; mf < 2; mf++) {
                uint32_t off = (uint32_t)(rowA[mf] * 128) +
                               (uint32_t)(colA ^ ((rowA[mf] & 7) * 16));
                LDSM4(ah[mf][0], ah[mf][1], ah[mf][2], ah[mf][3], stb + ST_AHI + off);
                LDSM4(al[mf][0], al[mf][1], al[mf][2], al[mf][3], stb + ST_ALO + off);
            }
            uint32_t bh[2][2], bl[2][2];
            {
                uint32_t off = (uint32_t)(rowB * 128) +
                               (uint32_t)(colB ^ ((rowB & 7) * 16));
                LDSM4(bh[0][0], bh[0][1], bh[1][0], bh[1][1], sbase + CB_HI + off);
                LDSM4(bl[0][0], bl[0][1], bl[1][0], bl[1][1], sbase + CB_LO + off);
            }
#pragma unroll
            for (int mf = 0; mf < 2; mf++)
#pragma unroll
                for (int nf = 0; nf < 2; nf++) {
                    MMA_BF16(acc[mf][nf], ah[mf], bh[nf]);
                    MMA_BF16(acc[mf][nf], ah[mf], bl[nf]);
                    MMA_BF16(acc[mf][nf], al[mf], bh[nf]);
                }
        }
        __syncthreads();
    }

    const int r = lid >> 2;
    const int cc = (lid & 3) * 2;
#pragma unroll
    for (int mf = 0; mf < 2; mf++) {
        int m1 = m0 + wm * 32 + mf * 16 + r;
        int m2 = m1 + 8;
        float bv1 = g_bias[m1];
        float bv2 = g_bias[m2];
#pragma unroll
        for (int nf = 0; nf < 2; nf++) {
            int p = p0 + wn * 16 + nf * 8 + cc;
            float2 v1 = make_float2(acc[mf][nf][0] + bv1, acc[mf][nf][1] + bv1);
            *(float2*)&g_y[((size_t)b * MID + m1) * P + p] = v1;
            float2 v2 = make_float2(acc[mf][nf][2] + bv2, acc[mf][nf][3] + bv2);
            *(float2*)&g_y[((size_t)b * MID + m2) * P + p] = v2;
        }
    }
}

// ---------------- K3: wgen1 via mma.sync, register-pipelined gather (R15, proven) ----------------
#define W1_AH   0
#define W1_AL   20480
#define W1_BH   40960
#define W1_BL   57344
#define W1_C4   73728
#define W1_CB   (W1_C4 + 320 * 16)
#define W1_TOTAL (W1_CB + 320 * 4)

__global__ __launch_bounds__(256) void wgen1_mma_kernel() {
    extern __shared__ char smem[];
    const uint32_t sbase = smem_u32(smem);
    int4*  s_c4 = (int4*)(smem + W1_C4);
    float* s_cb = (float*)(smem + W1_CB);
    const int tid = threadIdx.x;
    const int wid = tid >> 5;
    const int lid = tid & 31;
    const int b  = blockIdx.y;
    const int p0 = blockIdx.x * 128;
    const float* yb = g_y + (size_t)b * MID * P;

#pragma unroll
    for (int e = 0; e < 5; e++) {
        int idx = tid + e * 256;
        int c = idx >> 8, rem = idx & 255;
        int m = rem >> 3, kg = rem & 7;
        uint32_t dst = (uint32_t)(c * 4096 + m * 128) + (uint32_t)((kg * 16) ^ ((m & 7) * 16));
        size_t src = (size_t)m * MID + c * 64 + kg * 8;
        *(uint4*)(smem + W1_AH + dst) = *(const uint4*)&g_c1hi[src];
        *(uint4*)(smem + W1_AL + dst) = *(const uint4*)&g_c1lo[src];
    }
    for (int k = tid; k < MID; k += 256) {
        int ch, di, dj;
        if (k < 32) { ch = k; di = 0; dj = 0; }
        else {
            int cc = k - 32;
            int rr = cc / 9, t9 = cc - rr * 9;
            ch = 32 + rr;
            di = t9 / 3 - 1;
            dj = t9 - (t9 / 3) * 3 - 1;
        }
        s_c4[k] = make_int4(ch, di, dj, __float_as_int(g_bn1s[k]));
        s_cb[k] = g_bn1b[k];
    }
    __syncthreads();

    float acc[2][2][4];
#pragma unroll
    for (int i = 0; i < 2; i++)
#pragma unroll
        for (int j = 0; j < 2; j++)
#pragma unroll
            for (int q = 0; q < 4; q++) acc[i][j][q] = 0.f;

    const int rowA[2] = { (lid & 15), 16 + (lid & 15) };
    const int c16A = (lid >> 4) * 16;
    const int rowB = wid * 16 + ((lid >> 4) * 8) + (lid & 7);
    const int c16B = ((lid >> 3) & 1) * 16;

    const int fpx = tid & 127;
    const int fkh = (tid >> 7) * 32;
    const int pi = (p0 + fpx) >> 6;
    const int pj = (p0 + fpx) & 63;

    auto gather = [&](int c, float* vb) {
        const int kk = c * 64;
#pragma unroll
        for (int e = 0; e < 16; e++) {
            int k0 = kk + fkh + 2 * e;
            int4 c40 = s_c4[k0];
            int4 c41 = s_c4[k0 + 1];
            int i0 = pi + c40.y, j0 = pj + c40.z;
            i0 = min(abs(i0), 126 - i0); j0 = min(abs(j0), 126 - j0);
            int i1 = pi + c41.y, j1 = pj + c41.z;
            i1 = min(abs(i1), 126 - i1); j1 = min(abs(j1), 126 - j1);
            vb[2 * e]     = yb[(size_t)c40.x * P + (i0 << 6) + j0];
            vb[2 * e + 1] = yb[(size_t)c41.x * P + (i1 << 6) + j1];
        }
    };
    auto convert = [&](int c, const float* vb) {
        const int kk = c * 64;
#pragma unroll
        for (int e = 0; e < 16; e++) {
            int kloc0 = fkh + 2 * e;
            int k0 = kk + kloc0;
            float s0 = __int_as_float(s_c4[k0].w);
            float s1 = __int_as_float(s_c4[k0 + 1].w);
            float h0 = fmaxf(fmaf(vb[2 * e],     s0, s_cb[k0]),     0.f);
            float h1 = fmaxf(fmaf(vb[2 * e + 1], s1, s_cb[k0 + 1]), 0.f);
            __nv_bfloat16 hh0 = __float2bfloat16(h0);
            __nv_bfloat16 hh1 = __float2bfloat16(h1);
            __nv_bfloat16 ll0 = __float2bfloat16(h0 - __bfloat162float(hh0));
            __nv_bfloat16 ll1 = __float2bfloat16(h1 - __bfloat162float(hh1));
            uint32_t dst = (uint32_t)(fpx * 128) + (uint32_t)((kloc0 * 2) ^ ((fpx & 7) * 16));
            *(__nv_bfloat162*)(smem + W1_BH + dst) = __nv_bfloat162(hh0, hh1);
            *(__nv_bfloat162*)(smem + W1_BL + dst) = __nv_bfloat162(ll0, ll1);
        }
    };

    float vbuf[32], vnext[32];
    gather(0, vbuf);
#pragma unroll
    for (int c = 0; c < 5; c++) {
        convert(c, vbuf);
        __syncthreads();
        if (c < 4) gather(c + 1, vnext);

        const uint32_t abase = (uint32_t)(c * 4096);
#pragma unroll
        for (int ks = 0; ks < 4; ks++) {
            const int colA = ks * 32 + c16A;
            const int colB = ks * 32 + c16B;
            uint32_t ah[2][4], al[2][4];
#pragma unroll
            for (int mf = 0; mf < 2; mf++) {
                uint32_t off = abase + (uint32_t)(rowA[mf] * 128) +
                               (uint32_t)(colA ^ ((rowA[mf] & 7) * 16));
                LDSM4(ah[mf][0], ah[mf][1], ah[mf][2], ah[mf][3], sbase + W1_AH + off);
                LDSM4(al[mf][0], al[mf][1], al[mf][2], al[mf][3], sbase + W1_AL + off);
            }
            uint32_t bh[2][2], bl[2][2];
            {
                uint32_t off = (uint32_t)(rowB * 128) + (uint32_t)(colB ^ ((rowB & 7) * 16));
                LDSM4(bh[0][0], bh[0][1], bh[1][0], bh[1][1], sbase + W1_BH + off);
                LDSM4(bl[0][0], bl[0][1], bl[1][0], bl[1][1], sbase + W1_BL + off);
            }
#pragma unroll
            for (int mf = 0; mf < 2; mf++)
#pragma unroll
                for (int nf = 0; nf < 2; nf++) {
                    MMA_BF16(acc[mf][nf], ah[mf], bh[nf]);
                    MMA_BF16(acc[mf][nf], ah[mf], bl[nf]);
                    MMA_BF16(acc[mf][nf], al[mf], bh[nf]);
                }
        }
        __syncthreads();
#pragma unroll
        for (int e = 0; e < 32; e++) vbuf[e] = vnext[e];
    }

    const int r = lid >> 2;
    const int c2 = (lid & 3) * 2;
#pragma unroll
    for (int mf = 0; mf < 2; mf++) {
        int g1 = mf * 16 + r;
        int g2 = g1 + 8;
        float s1 = g_bn2s[g1], sb1 = g_bn2b[g1];
        float s2 = g_bn2s[g2], sb2 = g_bn2b[g2];
#pragma unroll
        for (int nf = 0; nf < 2; nf++) {
            int p = p0 + wid * 16 + nf * 8 + c2;
            size_t base0 = ((size_t)b * P + p) * GG;
            size_t base1 = base0 + GG;
            float t00 = fmaxf(fmaf(acc[mf][nf][0], s1, sb1), 0.f);
            float t01 = fmaxf(fmaf(acc[mf][nf][1], s1, sb1), 0.f);
            float t10 = fmaxf(fmaf(acc[mf][nf][2], s2, sb2), 0.f);
            float t11 = fmaxf(fmaf(acc[mf][nf][3], s2, sb2), 0.f);
            __nv_bfloat16 h;
            h = __float2bfloat16(t00); g_thi[base0 + g1] = h;
            g_tlo[base0 + g1] = __float2bfloat16(t00 - __bfloat162float(h));
            h = __float2bfloat16(t01); g_thi[base1 + g1] = h;
            g_tlo[base1 + g1] = __float2bfloat16(t01 - __bfloat162float(h));
            h = __float2bfloat16(t10); g_thi[base0 + g2] = h;
            g_tlo[base0 + g2] = __float2bfloat16(t10 - __bfloat162float(h));
            h = __float2bfloat16(t11); g_thi[base1 + g2] = h;
            g_tlo[base1 + g2] = __float2bfloat16(t11 - __bfloat162float(h));
        }
    }
}

// ---------------- K4: wgen2 via mma.sync (R13 exact, proven) ----------------
#define W2_AH 0
#define W2_AL 12288
#define W2_BH 24576
#define W2_BL 40960
#define W2_TOTAL 57344

__global__ __launch_bounds__(256) void wgen2_mma_kernel(const float* __restrict__ cb2) {
    extern __shared__ char smem[];
    const uint32_t sbase = smem_u32(smem);
    const int tid = threadIdx.x;
    const int wid = tid >> 5;
    const int lid = tid & 31;
    const int b  = blockIdx.z;
    const int o0 = blockIdx.y * 96;
    const int p0 = blockIdx.x * 128;
    const int wm = wid & 1;
    const int wn = wid >> 1;

    for (int idx = tid; idx < 96 * 4; idx += 256) {
        int row = idx >> 2, c16 = (idx & 3) * 16;
        uint32_t dst = (uint32_t)(row * 128) + (uint32_t)(c16 ^ ((row & 7) * 16));
        size_t src = (size_t)(o0 + row) * GG + (c16 >> 1);
        *(uint4*)(smem + W2_AH + dst) = *(const uint4*)&g_c2hi[src];
        *(uint4*)(smem + W2_AL + dst) = *(const uint4*)&g_c2lo[src];
    }
    for (int idx = tid; idx < 128 * 4; idx += 256) {
        int row = idx >> 2, c16 = (idx & 3) * 16;
        uint32_t dst = (uint32_t)(row * 128) + (uint32_t)(c16 ^ ((row & 7) * 16));
        size_t src = ((size_t)b * P + p0 + row) * GG + (c16 >> 1);
        *(uint4*)(smem + W2_BH + dst) = *(const uint4*)&g_thi[src];
        *(uint4*)(smem + W2_BL + dst) = *(const uint4*)&g_tlo[src];
    }
    __syncthreads();

    float acc[3][4][4];
#pragma unroll
    for (int i = 0; i < 3; i++)
#pragma unroll
        for (int j = 0; j < 4; j++)
#pragma unroll
            for (int q = 0; q < 4; q++) acc[i][j][q] = 0.f;

    int rowA[3];
#pragma unroll
    for (int mf = 0; mf < 3; mf++) rowA[mf] = wm * 48 + mf * 16 + (lid & 15);
    const int c16A = (lid >> 4) * 16;
    int rowB[2];
#pragma unroll
    for (int nfp = 0; nfp < 2; nfp++)
        rowB[nfp] = wn * 32 + nfp * 16 + ((lid >> 4) * 8) + (lid & 7);
    const int c16B = ((lid >> 3) & 1) * 16;

#pragma unroll
    for (int ks = 0; ks < 2; ks++) {
        const int colA = ks * 32 + c16A;
        const int colB = ks * 32 + c16B;
        uint32_t ah[3][4], al[3][4];
#pragma unroll
        for (int mf = 0; mf < 3; mf++) {
            uint32_t off = (uint32_t)(rowA[mf] * 128) +
                           (uint32_t)(colA ^ ((rowA[mf] & 7) * 16));
            LDSM4(ah[mf][0], ah[mf][1], ah[mf][2], ah[mf][3], sbase + W2_AH + off);
            LDSM4(al[mf][0], al[mf][1], al[mf][2], al[mf][3], sbase + W2_AL + off);
        }
        uint32_t bh[4][2], bl[4][2];
#pragma unroll
        for (int nfp = 0; nfp < 2; nfp++) {
            uint32_t off = (uint32_t)(rowB[nfp] * 128) +
                           (uint32_t)(colB ^ ((rowB[nfp] & 7) * 16));
            LDSM4(bh[2 * nfp][0], bh[2 * nfp][1], bh[2 * nfp + 1][0], bh[2 * nfp + 1][1],
                  sbase + W2_BH + off);
            LDSM4(bl[2 * nfp][0], bl[2 * nfp][1], bl[2 * nfp + 1][0], bl[2 * nfp + 1][1],
                  sbase + W2_BL + off);
        }
#pragma unroll
        for (int mf = 0; mf < 3; mf++)
#pragma unroll
            for (int nf = 0; nf < 4; nf++) {
                MMA_BF16(acc[mf][nf], ah[mf], bh[nf]);
                MMA_BF16(acc[mf][nf], ah[mf], bl[nf]);
                MMA_BF16(acc[mf][nf], al[mf], bh[nf]);
            }
    }

    const int r = lid >> 2;
    const int cc = (lid & 3) * 2;
#pragma unroll
    for (int mf = 0; mf < 3; mf++) {
        int m1 = o0 + wm * 48 + mf * 16 + r;
        int m2 = m1 + 8;
        float bv1 = cb2[m1], bv2 = cb2[m2];
#pragma unroll
        for (int nf = 0; nf < 4; nf++) {
            int p = p0 + wn * 32 + nf * 8 + cc;
            float2 v1 = make_float2(acc[mf][nf][0] + bv1, acc[mf][nf][1] + bv1);
            *(float2*)&g_w[((size_t)b * WOUT + m1) * P + p] = v1;
            float2 v2 = make_float2(acc[mf][nf][2] + bv2, acc[mf][nf][3] + bv2);
            *(float2*)&g_w[((size_t)b * WOUT + m2) * P + p] = v2;
        }
    }
}

// ---------------- K5: local grouped 3x3 conv (zero pad) — R13 exact ----------------
__global__ __launch_bounds__(256) void localconv_kernel(float* __restrict__ out) {
    const int bg = blockIdx.y;
    const int b = bg >> 5, g = bg & 31;
    const int p = blockIdx.x * 256 + threadIdx.x;
    const int i = p >> 6, j = p & 63;

    const float* wv = g_w + ((size_t)b * WOUT + g * 9) * P + p;
    float w[9];
#pragma unroll
    for (int k = 0; k < 9; k++) w[k] = wv[(size_t)k * P];

    const float* x3 = g_y + ((size_t)b * MID + 64 + g * SHAREC) * P;
    float* ob = out + ((size_t)b * OUTC + g * SHAREC) * P + p;

#pragma unroll
    for (int s = 0; s < SHAREC; s++) {
        const float* xc = x3 + (size_t)s * P;
        float acc = 0.f;
#pragma unroll
        for (int ki = 0; ki < 3; ki++) {
            int ii = i + ki - 1;
            if (ii < 0 || ii > 63) continue;
#pragma unroll
            for (int kj = 0; kj < 3; kj++) {
                int jj = j + kj - 1;
                if (jj < 0 || jj > 63) continue;
                acc += xc[(ii << 6) + jj] * w[ki * 3 + kj];
            }
        }
        ob[(size_t)s * P] = acc;
    }
}

// ---------------- launch ----------------
extern "C" void kernel_launch(void* const* d_in, const int* in_sizes, int n_in,
                              void* d_out, int out_size) {
    const float* x     = (const float*)d_in[0];
    const float* w1    = (const float*)d_in[1];
    const float* b1    = (const float*)d_in[2];
    const float* w2    = (const float*)d_in[3];
    const float* b2    = (const float*)d_in[4];
    const float* w3    = (const float*)d_in[5];
    const float* b3    = (const float*)d_in[6];
    const float* bn1_g = (const float*)d_in[7];
    const float* bn1_b = (const float*)d_in[8];
    const float* bn1_m = (const float*)d_in[9];
    const float* bn1_v = (const float*)d_in[10];
    const float* cw1   = (const float*)d_in[11];
    const float* bn2_g = (const float*)d_in[12];
    const float* bn2_b = (const float*)d_in[13];
    const float* bn2_m = (const float*)d_in[14];
    const float* bn2_v = (const float*)d_in[15];
    const float* cw2   = (const float*)d_in[16];
    const float* cb2   = (const float*)d_in[17];
    float* out = (float*)d_out;

    static int smem_set = 0;
    if (!smem_set) {
        cudaFuncSetAttribute(conv_mma_kernel,
                             cudaFuncAttributeMaxDynamicSharedMemorySize, SM_TOTAL);
        cudaFuncSetAttribute(wgen1_mma_kernel,
                             cudaFuncAttributeMaxDynamicSharedMemorySize, W1_TOTAL);
        cudaFuncSetAttribute(wgen2_mma_kernel,
                             cudaFuncAttributeMaxDynamicSharedMemorySize, W2_TOTAL);
        smem_set = 1;
    }

    {
        int total = MIDP * CIN + GG * MID + WOUT * GG + MIDP;
        pack_kernel<<<(total + 255) / 256, 256>>>(w1, w2, w3, cw1, cw2,
                                                  b1, b2, b3,
                                                  bn1_g, bn1_b, bn1_m, bn1_v,
                                                  bn2_g, bn2_b, bn2_m, bn2_v);
    }
    {
        dim3 grid(P / 64, MID / 64, BB);      // 64 x 5 x 8
        conv_mma_kernel<<<grid, 256, SM_TOTAL>>>(x);
    }
    {
        dim3 grid(P / 128, BB);               // 32 x 8
        wgen1_mma_kernel<<<grid, 256, W1_TOTAL>>>();
    }
    {
        dim3 grid(P / 128, WOUT / 96, BB);    // 32 x 3 x 8
        wgen2_mma_kernel<<<grid, 256, W2_TOTAL>>>(cb2);
    }
    {
        dim3 grid(P / 256, BB * GG);          // 16 x 256
        localconv_kernel<<<grid, 256>>>(out);
    }
}

// round 17
// speedup vs baseline: 1.1237x; 1.1237x over previous
#include <cuda_runtime.h>
#include <cuda_bf16.h>
#include <math.h>
#include <stdint.h>

#define BB    8
#define CIN   256
#define OUTC  256
#define SHAREC 8
#define GG    32
#define MID   320
#define MIDP  384
#define WOUT  288
#define P     4096

// ---------------- scratch (static device arrays; no allocation) ----------------
__device__ float g_y[(size_t)BB * MID * P];      // conv1x1 outputs [b][c][p]
__device__ float g_w[(size_t)BB * WOUT * P];     // per-pixel kernels [b][o][p]
__device__ float g_bias[MIDP];
__device__ float g_bn1s[MID];
__device__ float g_bn1b[MID];
__device__ float g_bn2s[GG];
__device__ float g_bn2b[GG];
__device__ __nv_bfloat16 g_whi[MIDP * CIN];      // conv weights hi/lo, [m][k]
__device__ __nv_bfloat16 g_wlo[MIDP * CIN];
__device__ __nv_bfloat16 g_c1hi[GG * MID];       // cw1 hi/lo, [g][k]
__device__ __nv_bfloat16 g_c1lo[GG * MID];
__device__ __nv_bfloat16 g_c2hi[WOUT * GG];      // cw2 hi/lo, [o][k]
__device__ __nv_bfloat16 g_c2lo[WOUT * GG];
__device__ __nv_bfloat16 g_thi[(size_t)BB * P * GG];   // t hi/lo: [b][p][g]
__device__ __nv_bfloat16 g_tlo[(size_t)BB * P * GG];

__device__ __forceinline__ uint32_t smem_u32(const void* p) {
    uint32_t a;
    asm("{ .reg .u64 t; cvta.to.shared.u64 t, %1; cvt.u32.u64 %0, t; }" : "=r"(a) : "l"(p));
    return a;
}

#define LDSM4(r0, r1, r2, r3, addr) \
    asm volatile("ldmatrix.sync.aligned.m8n8.x4.shared.b16 {%0,%1,%2,%3}, [%4];" \
        : "=r"(r0), "=r"(r1), "=r"(r2), "=r"(r3) : "r"(addr))

#define MMA_BF16(d, a, b) \
    asm volatile("mma.sync.aligned.m16n8k16.row.col.f32.bf16.bf16.f32 " \
        "{%0,%1,%2,%3}, {%4,%5,%6,%7}, {%8,%9}, {%0,%1,%2,%3};" \
        : "+f"((d)[0]), "+f"((d)[1]), "+f"((d)[2]), "+f"((d)[3]) \
        : "r"((a)[0]), "r"((a)[1]), "r"((a)[2]), "r"((a)[3]), "r"((b)[0]), "r"((b)[1]))

#define CP_ASYNC16(saddr, gptr) \
    asm volatile("cp.async.cg.shared.global [%0], [%1], 16;" :: "r"(saddr), "l"(gptr))
#define CP_COMMIT() asm volatile("cp.async.commit_group;" ::: "memory")
#define CP_WAIT1()  asm volatile("cp.async.wait_group 1;" ::: "memory")
#define CP_WAIT0()  asm volatile("cp.async.wait_group 0;" ::: "memory")

// ---------------- K0: pack + split weights + fold BN (single launch) ----------------
__global__ __launch_bounds__(256) void pack_kernel(const float* __restrict__ w1,
                                                   const float* __restrict__ w2,
                                                   const float* __restrict__ w3,
                                                   const float* __restrict__ cw1,
                                                   const float* __restrict__ cw2,
                                                   const float* __restrict__ b1,
                                                   const float* __restrict__ b2,
                                                   const float* __restrict__ b3,
                                                   const float* __restrict__ bn1_g,
                                                   const float* __restrict__ bn1_b,
                                                   const float* __restrict__ bn1_m,
                                                   const float* __restrict__ bn1_v,
                                                   const float* __restrict__ bn2_g,
                                                   const float* __restrict__ bn2_b,
                                                   const float* __restrict__ bn2_m,
                                                   const float* __restrict__ bn2_v) {
    int idx = blockIdx.x * 256 + threadIdx.x;
    if (idx < MIDP * CIN) {
        int c = idx >> 8;
        int k = idx & 255;
        float v = 0.f;
        if (c < 32)       v = w1[c * CIN + k];
        else if (c < 64)  v = w2[(c - 32) * CIN + k];
        else if (c < MID) v = w3[(c - 64) * CIN + k];
        __nv_bfloat16 hi = __float2bfloat16(v);
        g_whi[idx] = hi;
        g_wlo[idx] = __float2bfloat16(v - __bfloat162float(hi));
    } else if (idx < MIDP * CIN + GG * MID) {
        int j = idx - MIDP * CIN;
        float v = cw1[j];
        __nv_bfloat16 hi = __float2bfloat16(v);
        g_c1hi[j] = hi;
        g_c1lo[j] = __float2bfloat16(v - __bfloat162float(hi));
    } else if (idx < MIDP * CIN + GG * MID + WOUT * GG) {
        int j = idx - MIDP * CIN - GG * MID;
        float v = cw2[j];
        __nv_bfloat16 hi = __float2bfloat16(v);
        g_c2hi[j] = hi;
        g_c2lo[j] = __float2bfloat16(v - __bfloat162float(hi));
    } else {
        int c = idx - MIDP * CIN - GG * MID - WOUT * GG;
        if (c < MID) {
            g_bias[c] = (c < 32) ? b1[c] : (c < 64) ? b2[c - 32] : b3[c - 64];
            float s = bn1_g[c] * rsqrtf(bn1_v[c] + 1e-5f);
            g_bn1s[c] = s;
            g_bn1b[c] = bn1_b[c] - bn1_m[c] * s;
            if (c < GG) {
                float s2 = bn2_g[c] * rsqrtf(bn2_v[c] + 1e-5f);
                g_bn2s[c] = s2;
                g_bn2b[c] = bn2_b[c] - bn2_m[c] * s2;
            }
        } else if (c < MIDP) {
            g_bias[c] = 0.f;
        }
    }
}

// ---------------- K1: conv1x1 split-bf16 GEMM, M128 x N64, fused x convert (R15/R11 proven) ----
#define KC 64
#define ST_AHI 0
#define ST_ALO 16384
#define ST_X   32768
#define STAGE  49152
#define CB_HI  98304
#define CB_LO  106496
#define SM_TOTAL 114688

__global__ __launch_bounds__(256, 2) void conv_mma_kernel(const float* __restrict__ x) {
    extern __shared__ char smem[];
    const uint32_t sbase = smem_u32(smem);
    const int tid = threadIdx.x;
    const int wid = tid >> 5;
    const int lid = tid & 31;
    const int b  = blockIdx.z;
    const int m0 = blockIdx.y * 128;
    const int p0 = blockIdx.x * 64;
    const int wm = wid & 3;
    const int wn = wid >> 2;

    float acc[2][4][4];
#pragma unroll
    for (int i = 0; i < 2; i++)
#pragma unroll
        for (int j = 0; j < 4; j++)
#pragma unroll
            for (int q = 0; q < 4; q++) acc[i][j][q] = 0.f;

    const int rowA[2] = { wm * 32 + (lid & 15), wm * 32 + 16 + (lid & 15) };
    const int c16A = (lid >> 4) * 16;
    int rowB[2];
#pragma unroll
    for (int nfp = 0; nfp < 2; nfp++)
        rowB[nfp] = wn * 32 + nfp * 16 + ((lid >> 4) * 8) + (lid & 7);
    const int c16B = ((lid >> 3) & 1) * 16;

    const int rowL = tid >> 3;
    const int ccL  = (tid & 7) * 16;
    uint32_t ldstA[4];
    const __nv_bfloat16 *srcAh[4], *srcAl[4];
#pragma unroll
    for (int e = 0; e < 4; e++) {
        int row = rowL + e * 32;
        ldstA[e] = (uint32_t)(row * 128) + (uint32_t)(ccL ^ ((row & 7) * 16));
        size_t sA = (size_t)(m0 + row) * CIN + (ccL >> 1);
        srcAh[e] = &g_whi[sA]; srcAl[e] = &g_wlo[sA];
    }
    const float* xbase = x + (size_t)b * CIN * P + p0;
    const int kxL = tid >> 4;
    const int uxL = (tid & 15) * 16;

    auto issue = [&](int c, int s) {
        const uint32_t stb = sbase + (uint32_t)(s * STAGE);
        const int koff = c * KC;
#pragma unroll
        for (int e = 0; e < 4; e++) {
            CP_ASYNC16(stb + ST_AHI + ldstA[e], srcAh[e] + koff);
            CP_ASYNC16(stb + ST_ALO + ldstA[e], srcAl[e] + koff);
        }
#pragma unroll
        for (int e = 0; e < 4; e++) {
            int kx = kxL + e * 16;
            CP_ASYNC16(stb + ST_X + (uint32_t)(kx * 256) + (uint32_t)uxL,
                       xbase + (size_t)(koff + kx) * P + (uxL >> 2));
        }
        CP_COMMIT();
    };

    const int cvp = tid & 63;
    const int cvk = (tid >> 6) * 16;

    issue(0, 0);
    for (int c = 0; c < 4; c++) {
        if (c < 3) { issue(c + 1, (c + 1) & 1); CP_WAIT1(); }
        else       { CP_WAIT0(); }
        __syncthreads();

        {
            const char* xs = smem + (c & 1) * STAGE + ST_X;
#pragma unroll
            for (int e = 0; e < 8; e++) {
                int k = cvk + 2 * e;
                float f0 = *(const float*)(xs + k * 256 + cvp * 4);
                float f1 = *(const float*)(xs + (k + 1) * 256 + cvp * 4);
                __nv_bfloat16 h0 = __float2bfloat16(f0);
                __nv_bfloat16 h1 = __float2bfloat16(f1);
                __nv_bfloat16 l0 = __float2bfloat16(f0 - __bfloat162float(h0));
                __nv_bfloat16 l1 = __float2bfloat16(f1 - __bfloat162float(h1));
                uint32_t d = (uint32_t)(cvp * 128) + (uint32_t)((2 * k) ^ ((cvp & 7) * 16));
                *(__nv_bfloat162*)(smem + CB_HI + d) = __nv_bfloat162(h0, h1);
                *(__nv_bfloat162*)(smem + CB_LO + d) = __nv_bfloat162(l0, l1);
            }
        }
        __syncthreads();

        const uint32_t stb = sbase + (uint32_t)((c & 1) * STAGE);
#pragma unroll
        for (int ks = 0; ks < 4; ks++) {
            const int colA = (ks * 32 + c16A);
            const int colB = (ks * 32 + c16B);
            uint32_t ah[2][4], al[2][4];
#pragma unroll
            for (int mf = 0; mf < 2; mf++) {
                uint32_t off = (uint32_t)(rowA[mf] * 128) +
                               (uint32_t)(colA ^ ((rowA[mf] & 7) * 16));
                LDSM4(ah[mf][0], ah[mf][1], ah[mf][2], ah[mf][3], stb + ST_AHI + off);
                LDSM4(al[mf][0], al[mf][1], al[mf][2], al[mf][3], stb + ST_ALO + off);
            }
            uint32_t bh[4][2], bl[4][2];
#pragma unroll
            for (int nfp = 0; nfp < 2; nfp++) {
                uint32_t off = (uint32_t)(rowB[nfp] * 128) +
                               (uint32_t)(colB ^ ((rowB[nfp] & 7) * 16));
                LDSM4(bh[2 * nfp][0], bh[2 * nfp][1], bh[2 * nfp + 1][0], bh[2 * nfp + 1][1],
                      sbase + CB_HI + off);
                LDSM4(bl[2 * nfp][0], bl[2 * nfp][1], bl[2 * nfp + 1][0], bl[2 * nfp + 1][1],
                      sbase + CB_LO + off);
            }
#pragma unroll
            for (int mf = 0; mf < 2; mf++)
#pragma unroll
                for (int nf = 0; nf < 4; nf++) {
                    MMA_BF16(acc[mf][nf], ah[mf], bh[nf]);
                    MMA_BF16(acc[mf][nf], ah[mf], bl[nf]);
                    MMA_BF16(acc[mf][nf], al[mf], bh[nf]);
                }
        }
        __syncthreads();
    }

    const int r = lid >> 2;
    const int cc = (lid & 3) * 2;
#pragma unroll
    for (int mf = 0; mf < 2; mf++) {
        int m1 = m0 + wm * 32 + mf * 16 + r;
        int m2 = m1 + 8;
        float bv1 = (m1 < MID) ? g_bias[m1] : 0.f;
        float bv2 = (m2 < MID) ? g_bias[m2] : 0.f;
#pragma unroll
        for (int nf = 0; nf < 4; nf++) {
            int p = p0 + wn * 32 + nf * 8 + cc;
            if (m1 < MID) {
                float2 v = make_float2(acc[mf][nf][0] + bv1, acc[mf][nf][1] + bv1);
                *(float2*)&g_y[((size_t)b * MID + m1) * P + p] = v;
            }
            if (m2 < MID) {
                float2 v = make_float2(acc[mf][nf][2] + bv2, acc[mf][nf][3] + bv2);
                *(float2*)&g_y[((size_t)b * MID + m2) * P + p] = v;
            }
        }
    }
}

// ---------------- K3: wgen1 via mma.sync, register-pipelined gather (R15, proven) ----------------
#define W1_AH   0
#define W1_AL   20480
#define W1_BH   40960
#define W1_BL   57344
#define W1_C4   73728
#define W1_CB   (W1_C4 + 320 * 16)
#define W1_TOTAL (W1_CB + 320 * 4)

__global__ __launch_bounds__(256) void wgen1_mma_kernel() {
    extern __shared__ char smem[];
    const uint32_t sbase = smem_u32(smem);
    int4*  s_c4 = (int4*)(smem + W1_C4);
    float* s_cb = (float*)(smem + W1_CB);
    const int tid = threadIdx.x;
    const int wid = tid >> 5;
    const int lid = tid & 31;
    const int b  = blockIdx.y;
    const int p0 = blockIdx.x * 128;
    const float* yb = g_y + (size_t)b * MID * P;

#pragma unroll
    for (int e = 0; e < 5; e++) {
        int idx = tid + e * 256;
        int c = idx >> 8, rem = idx & 255;
        int m = rem >> 3, kg = rem & 7;
        uint32_t dst = (uint32_t)(c * 4096 + m * 128) + (uint32_t)((kg * 16) ^ ((m & 7) * 16));
        size_t src = (size_t)m * MID + c * 64 + kg * 8;
        *(uint4*)(smem + W1_AH + dst) = *(const uint4*)&g_c1hi[src];
        *(uint4*)(smem + W1_AL + dst) = *(const uint4*)&g_c1lo[src];
    }
    for (int k = tid; k < MID; k += 256) {
        int ch, di, dj;
        if (k < 32) { ch = k; di = 0; dj = 0; }
        else {
            int cc = k - 32;
            int rr = cc / 9, t9 = cc - rr * 9;
            ch = 32 + rr;
            di = t9 / 3 - 1;
            dj = t9 - (t9 / 3) * 3 - 1;
        }
        s_c4[k] = make_int4(ch, di, dj, __float_as_int(g_bn1s[k]));
        s_cb[k] = g_bn1b[k];
    }
    __syncthreads();

    float acc[2][2][4];
#pragma unroll
    for (int i = 0; i < 2; i++)
#pragma unroll
        for (int j = 0; j < 2; j++)
#pragma unroll
            for (int q = 0; q < 4; q++) acc[i][j][q] = 0.f;

    const int rowA[2] = { (lid & 15), 16 + (lid & 15) };
    const int c16A = (lid >> 4) * 16;
    const int rowB = wid * 16 + ((lid >> 4) * 8) + (lid & 7);
    const int c16B = ((lid >> 3) & 1) * 16;

    const int fpx = tid & 127;
    const int fkh = (tid >> 7) * 32;
    const int pi = (p0 + fpx) >> 6;
    const int pj = (p0 + fpx) & 63;

    auto gather = [&](int c, float* vb) {
        const int kk = c * 64;
#pragma unroll
        for (int e = 0; e < 16; e++) {
            int k0 = kk + fkh + 2 * e;
            int4 c40 = s_c4[k0];
            int4 c41 = s_c4[k0 + 1];
            int i0 = pi + c40.y, j0 = pj + c40.z;
            i0 = min(abs(i0), 126 - i0); j0 = min(abs(j0), 126 - j0);
            int i1 = pi + c41.y, j1 = pj + c41.z;
            i1 = min(abs(i1), 126 - i1); j1 = min(abs(j1), 126 - j1);
            vb[2 * e]     = yb[(size_t)c40.x * P + (i0 << 6) + j0];
            vb[2 * e + 1] = yb[(size_t)c41.x * P + (i1 << 6) + j1];
        }
    };
    auto convert = [&](int c, const float* vb) {
        const int kk = c * 64;
#pragma unroll
        for (int e = 0; e < 16; e++) {
            int kloc0 = fkh + 2 * e;
            int k0 = kk + kloc0;
            float s0 = __int_as_float(s_c4[k0].w);
            float s1 = __int_as_float(s_c4[k0 + 1].w);
            float h0 = fmaxf(fmaf(vb[2 * e],     s0, s_cb[k0]),     0.f);
            float h1 = fmaxf(fmaf(vb[2 * e + 1], s1, s_cb[k0 + 1]), 0.f);
            __nv_bfloat16 hh0 = __float2bfloat16(h0);
            __nv_bfloat16 hh1 = __float2bfloat16(h1);
            __nv_bfloat16 ll0 = __float2bfloat16(h0 - __bfloat162float(hh0));
            __nv_bfloat16 ll1 = __float2bfloat16(h1 - __bfloat162float(hh1));
            uint32_t dst = (uint32_t)(fpx * 128) + (uint32_t)((kloc0 * 2) ^ ((fpx & 7) * 16));
            *(__nv_bfloat162*)(smem + W1_BH + dst) = __nv_bfloat162(hh0, hh1);
            *(__nv_bfloat162*)(smem + W1_BL + dst) = __nv_bfloat162(ll0, ll1);
        }
    };

    float vbuf[32], vnext[32];
    gather(0, vbuf);
#pragma unroll
    for (int c = 0; c < 5; c++) {
        convert(c, vbuf);
        __syncthreads();
        if (c < 4) gather(c + 1, vnext);

        const uint32_t abase = (uint32_t)(c * 4096);
#pragma unroll
        for (int ks = 0; ks < 4; ks++) {
            const int colA = ks * 32 + c16A;
            const int colB = ks * 32 + c16B;
            uint32_t ah[2][4], al[2][4];
#pragma unroll
            for (int mf = 0; mf < 2; mf++) {
                uint32_t off = abase + (uint32_t)(rowA[mf] * 128) +
                               (uint32_t)(colA ^ ((rowA[mf] & 7) * 16));
                LDSM4(ah[mf][0], ah[mf][1], ah[mf][2], ah[mf][3], sbase + W1_AH + off);
                LDSM4(al[mf][0], al[mf][1], al[mf][2], al[mf][3], sbase + W1_AL + off);
            }
            uint32_t bh[2][2], bl[2][2];
            {
                uint32_t off = (uint32_t)(rowB * 128) + (uint32_t)(colB ^ ((rowB & 7) * 16));
                LDSM4(bh[0][0], bh[0][1], bh[1][0], bh[1][1], sbase + W1_BH + off);
                LDSM4(bl[0][0], bl[0][1], bl[1][0], bl[1][1], sbase + W1_BL + off);
            }
#pragma unroll
            for (int mf = 0; mf < 2; mf++)
#pragma unroll
                for (int nf = 0; nf < 2; nf++) {
                    MMA_BF16(acc[mf][nf], ah[mf], bh[nf]);
                    MMA_BF16(acc[mf][nf], ah[mf], bl[nf]);
                    MMA_BF16(acc[mf][nf], al[mf], bh[nf]);
                }
        }
        __syncthreads();
#pragma unroll
        for (int e = 0; e < 32; e++) vbuf[e] = vnext[e];
    }

    const int r = lid >> 2;
    const int c2 = (lid & 3) * 2;
#pragma unroll
    for (int mf = 0; mf < 2; mf++) {
        int g1 = mf * 16 + r;
        int g2 = g1 + 8;
        float s1 = g_bn2s[g1], sb1 = g_bn2b[g1];
        float s2 = g_bn2s[g2], sb2 = g_bn2b[g2];
#pragma unroll
        for (int nf = 0; nf < 2; nf++) {
            int p = p0 + wid * 16 + nf * 8 + c2;
            size_t base0 = ((size_t)b * P + p) * GG;
            size_t base1 = base0 + GG;
            float t00 = fmaxf(fmaf(acc[mf][nf][0], s1, sb1), 0.f);
            float t01 = fmaxf(fmaf(acc[mf][nf][1], s1, sb1), 0.f);
            float t10 = fmaxf(fmaf(acc[mf][nf][2], s2, sb2), 0.f);
            float t11 = fmaxf(fmaf(acc[mf][nf][3], s2, sb2), 0.f);
            __nv_bfloat16 h;
            h = __float2bfloat16(t00); g_thi[base0 + g1] = h;
            g_tlo[base0 + g1] = __float2bfloat16(t00 - __bfloat162float(h));
            h = __float2bfloat16(t01); g_thi[base1 + g1] = h;
            g_tlo[base1 + g1] = __float2bfloat16(t01 - __bfloat162float(h));
            h = __float2bfloat16(t10); g_thi[base0 + g2] = h;
            g_tlo[base0 + g2] = __float2bfloat16(t10 - __bfloat162float(h));
            h = __float2bfloat16(t11); g_thi[base1 + g2] = h;
            g_tlo[base1 + g2] = __float2bfloat16(t11 - __bfloat162float(h));
        }
    }
}

// ---------------- K4: wgen2 via mma.sync (R13 exact, proven) ----------------
#define W2_AH 0
#define W2_AL 12288
#define W2_BH 24576
#define W2_BL 40960
#define W2_TOTAL 57344

__global__ __launch_bounds__(256) void wgen2_mma_kernel(const float* __restrict__ cb2) {
    extern __shared__ char smem[];
    const uint32_t sbase = smem_u32(smem);
    const int tid = threadIdx.x;
    const int wid = tid >> 5;
    const int lid = tid & 31;
    const int b  = blockIdx.z;
    const int o0 = blockIdx.y * 96;
    const int p0 = blockIdx.x * 128;
    const int wm = wid & 1;
    const int wn = wid >> 1;

    for (int idx = tid; idx < 96 * 4; idx += 256) {
        int row = idx >> 2, c16 = (idx & 3) * 16;
        uint32_t dst = (uint32_t)(row * 128) + (uint32_t)(c16 ^ ((row & 7) * 16));
        size_t src = (size_t)(o0 + row) * GG + (c16 >> 1);
        *(uint4*)(smem + W2_AH + dst) = *(const uint4*)&g_c2hi[src];
        *(uint4*)(smem + W2_AL + dst) = *(const uint4*)&g_c2lo[src];
    }
    for (int idx = tid; idx < 128 * 4; idx += 256) {
        int row = idx >> 2, c16 = (idx & 3) * 16;
        uint32_t dst = (uint32_t)(row * 128) + (uint32_t)(c16 ^ ((row & 7) * 16));
        size_t src = ((size_t)b * P + p0 + row) * GG + (c16 >> 1);
        *(uint4*)(smem + W2_BH + dst) = *(const uint4*)&g_thi[src];
        *(uint4*)(smem + W2_BL + dst) = *(const uint4*)&g_tlo[src];
    }
    __syncthreads();

    float acc[3][4][4];
#pragma unroll
    for (int i = 0; i < 3; i++)
#pragma unroll
        for (int j = 0; j < 4; j++)
#pragma unroll
            for (int q = 0; q < 4; q++) acc[i][j][q] = 0.f;

    int rowA[3];
#pragma unroll
    for (int mf = 0; mf < 3; mf++) rowA[mf] = wm * 48 + mf * 16 + (lid & 15);
    const int c16A = (lid >> 4) * 16;
    int rowB[2];
#pragma unroll
    for (int nfp = 0; nfp < 2; nfp++)
        rowB[nfp] = wn * 32 + nfp * 16 + ((lid >> 4) * 8) + (lid & 7);
    const int c16B = ((lid >> 3) & 1) * 16;

#pragma unroll
    for (int ks = 0; ks < 2; ks++) {
        const int colA = ks * 32 + c16A;
        const int colB = ks * 32 + c16B;
        uint32_t ah[3][4], al[3][4];
#pragma unroll
        for (int mf = 0; mf < 3; mf++) {
            uint32_t off = (uint32_t)(rowA[mf] * 128) +
                           (uint32_t)(colA ^ ((rowA[mf] & 7) * 16));
            LDSM4(ah[mf][0], ah[mf][1], ah[mf][2], ah[mf][3], sbase + W2_AH + off);
            LDSM4(al[mf][0], al[mf][1], al[mf][2], al[mf][3], sbase + W2_AL + off);
        }
        uint32_t bh[4][2], bl[4][2];
#pragma unroll
        for (int nfp = 0; nfp < 2; nfp++) {
            uint32_t off = (uint32_t)(rowB[nfp] * 128) +
                           (uint32_t)(colB ^ ((rowB[nfp] & 7) * 16));
            LDSM4(bh[2 * nfp][0], bh[2 * nfp][1], bh[2 * nfp + 1][0], bh[2 * nfp + 1][1],
                  sbase + W2_BH + off);
            LDSM4(bl[2 * nfp][0], bl[2 * nfp][1], bl[2 * nfp + 1][0], bl[2 * nfp + 1][1],
                  sbase + W2_BL + off);
        }
#pragma unroll
        for (int mf = 0; mf < 3; mf++)
#pragma unroll
            for (int nf = 0; nf < 4; nf++) {
                MMA_BF16(acc[mf][nf], ah[mf], bh[nf]);
                MMA_BF16(acc[mf][nf], ah[mf], bl[nf]);
                MMA_BF16(acc[mf][nf], al[mf], bh[nf]);
            }
    }

    const int r = lid >> 2;
    const int cc = (lid & 3) * 2;
#pragma unroll
    for (int mf = 0; mf < 3; mf++) {
        int m1 = o0 + wm * 48 + mf * 16 + r;
        int m2 = m1 + 8;
        float bv1 = cb2[m1], bv2 = cb2[m2];
#pragma unroll
        for (int nf = 0; nf < 4; nf++) {
            int p = p0 + wn * 32 + nf * 8 + cc;
            float2 v1 = make_float2(acc[mf][nf][0] + bv1, acc[mf][nf][1] + bv1);
            *(float2*)&g_w[((size_t)b * WOUT + m1) * P + p] = v1;
            float2 v2 = make_float2(acc[mf][nf][2] + bv2, acc[mf][nf][3] + bv2);
            *(float2*)&g_w[((size_t)b * WOUT + m2) * P + p] = v2;
        }
    }
}

// ---------------- K5: local grouped 3x3 conv — 2 pixels/thread (float2 w loads) ----------------
__global__ __launch_bounds__(256) void localconv_kernel(float* __restrict__ out) {
    const int bg = blockIdx.y;
    const int b = bg >> 5, g = bg & 31;
    const int p = blockIdx.x * 512 + threadIdx.x * 2;
    const int i = p >> 6, j = p & 63;   // two pixels (i,j) and (i,j+1); j even so j+1 <= 63

    const float* wv = g_w + ((size_t)b * WOUT + g * 9) * P + p;
    float2 w[9];
#pragma unroll
    for (int k = 0; k < 9; k++) w[k] = *(const float2*)&wv[(size_t)k * P];

    const float* x3 = g_y + ((size_t)b * MID + 64 + g * SHAREC) * P;
    float* ob = out + ((size_t)b * OUTC + g * SHAREC) * P + p;

#pragma unroll
    for (int s = 0; s < SHAREC; s++) {
        const float* xc = x3 + (size_t)s * P;
        float a0 = 0.f, a1 = 0.f;
#pragma unroll
        for (int ki = 0; ki < 3; ki++) {
            int ii = i + ki - 1;
            if (ii < 0 || ii > 63) continue;
            const float* xr = xc + (ii << 6);
            // union of taps: columns j-1 .. j+2
            float v0 = (j >= 1)     ? xr[j - 1] : 0.f;
            float v1 = xr[j];
            float v2 = xr[j + 1];
            float v3 = (j + 2 <= 63) ? xr[j + 2] : 0.f;
            a0 += v0 * w[ki * 3 + 0].x + v1 * w[ki * 3 + 1].x + v2 * w[ki * 3 + 2].x;
            a1 += v1 * w[ki * 3 + 0].y + v2 * w[ki * 3 + 1].y + v3 * w[ki * 3 + 2].y;
        }
        *(float2*)&ob[(size_t)s * P] = make_float2(a0, a1);
    }
}

// ---------------- launch ----------------
extern "C" void kernel_launch(void* const* d_in, const int* in_sizes, int n_in,
                              void* d_out, int out_size) {
    const float* x     = (const float*)d_in[0];
    const float* w1    = (const float*)d_in[1];
    const float* b1    = (const float*)d_in[2];
    const float* w2    = (const float*)d_in[3];
    const float* b2    = (const float*)d_in[4];
    const float* w3    = (const float*)d_in[5];
    const float* b3    = (const float*)d_in[6];
    const float* bn1_g = (const float*)d_in[7];
    const float* bn1_b = (const float*)d_in[8];
    const float* bn1_m = (const float*)d_in[9];
    const float* bn1_v = (const float*)d_in[10];
    const float* cw1   = (const float*)d_in[11];
    const float* bn2_g = (const float*)d_in[12];
    const float* bn2_b = (const float*)d_in[13];
    const float* bn2_m = (const float*)d_in[14];
    const float* bn2_v = (const float*)d_in[15];
    const float* cw2   = (const float*)d_in[16];
    const float* cb2   = (const float*)d_in[17];
    float* out = (float*)d_out;

    static int smem_set = 0;
    if (!smem_set) {
        cudaFuncSetAttribute(conv_mma_kernel,
                             cudaFuncAttributeMaxDynamicSharedMemorySize, SM_TOTAL);
        cudaFuncSetAttribute(wgen1_mma_kernel,
                             cudaFuncAttributeMaxDynamicSharedMemorySize, W1_TOTAL);
        cudaFuncSetAttribute(wgen2_mma_kernel,
                             cudaFuncAttributeMaxDynamicSharedMemorySize, W2_TOTAL);
        smem_set = 1;
    }

    {
        int total = MIDP * CIN + GG * MID + WOUT * GG + MIDP;
        pack_kernel<<<(total + 255) / 256, 256>>>(w1, w2, w3, cw1, cw2,
                                                  b1, b2, b3,
                                                  bn1_g, bn1_b, bn1_m, bn1_v,
                                                  bn2_g, bn2_b, bn2_m, bn2_v);
    }
    {
        dim3 grid(P / 64, MIDP / 128, BB);    // 64 x 3 x 8
        conv_mma_kernel<<<grid, 256, SM_TOTAL>>>(x);
    }
    {
        dim3 grid(P / 128, BB);               // 32 x 8
        wgen1_mma_kernel<<<grid, 256, W1_TOTAL>>>();
    }
    {
        dim3 grid(P / 128, WOUT / 96, BB);    // 32 x 3 x 8
        wgen2_mma_kernel<<<grid, 256, W2_TOTAL>>>(cb2);
    }
    {
        dim3 grid(P / 512, BB * GG);          // 8 x 256
        localconv_kernel<<<grid, 256>>>(out);
    }
}